// round 7
// baseline (speedup 1.0000x reference)
#include <cuda_runtime.h>
#include <math.h>

#define BB 4
#define CC 64
#define HH 96
#define WW 320
#define HP 97   // conv rows 0..96 (row 96 = top kernel row on x[95])

// Scratch (static device globals: allowed; no runtime allocation)
__device__ float g_conv[BB*CC*HP*WW];   // ~31.8 MB
__device__ float g_mid [BB*CC*HH*WW];   // ~31.5 MB
__device__ float g_T   [BB*CC*16*WW];   // ~5.2 MB  (top-row conv at 16 special rows)

// rows f_d-1, f_d for f = {1,12,22,33,44,54,65,76}
__constant__ int c_R16[16] = {0,1, 11,12, 21,22, 32,33, 43,44, 53,54, 64,65, 75,76};

// ---- packed f32x2 helpers (sm_103a) ---------------------------------------
#define PACKF2(d, lo, hi) \
    asm("mov.b64 %0, {%1, %2};" : "=l"(d) : "r"(__float_as_uint(lo)), "r"(__float_as_uint(hi)))
#define UNPACKF2(lo, hi, s) do { unsigned _ulo, _uhi; \
    asm("mov.b64 {%0, %1}, %2;" : "=r"(_ulo), "=r"(_uhi) : "l"(s)); \
    lo = __uint_as_float(_ulo); hi = __uint_as_float(_uhi); } while (0)
#define FFMA2(d, a, b) \
    asm("fma.rn.f32x2 %0, %1, %2, %0;" : "+l"(d) : "l"(a), "l"(b))

// ---------------------------------------------------------------------------
// 3x3 SAME conv, zero-extended input, output rows 0..96 into g_conv.
// Block: 64 co x (8 rows x 32 cols) tile, 256 threads, each 8co x 8px.
// ci chunked by 8 (2 barriers / 8 ci). Inner math: packed fma.rn.f32x2.
// grid = (WW/32=10, ceil(HP/8)=13, BB)
// ---------------------------------------------------------------------------
__global__ __launch_bounds__(256, 1)
void conv3_kernel(const float* __restrict__ in_ext, const float* __restrict__ wk)
{
    const float* in = in_ext ? in_ext : g_mid;
    // Xs stride 35: lanes differ in (row, colg); addr = r*35 + cg*8 + m is
    // conflict-free across the warp for fixed m.
    __shared__ __align__(16) float Xs[8][10][35];                 // 11200 B
    __shared__ __align__(16) unsigned long long Ws2[8][9][64];    // 36864 B (w duplicated)

    const int x0  = blockIdx.x * 32;
    const int y0  = blockIdx.y * 8;
    const int b   = blockIdx.z;
    const int tid = threadIdx.x;
    const int cog  = tid >> 5;          // 0..7 : co group (8 co, uniform per warp)
    const int pg   = tid & 31;
    const int row  = pg >> 2;           // 0..7 : tile row
    const int colg = (pg & 3) * 8;      // 0,8,16,24 : col group (8 cols)

    unsigned long long acc2[8][4];
    #pragma unroll
    for (int i = 0; i < 8; i++)
        #pragma unroll
        for (int p = 0; p < 4; p++) acc2[i][p] = 0ull;

    #pragma unroll 1
    for (int ci0 = 0; ci0 < CC; ci0 += 8) {
        // ---- load 8-ci input tile with halo (zero-padded) ----
        for (int idx = tid; idx < 8 * 340; idx += 256) {
            int kk  = idx / 340;
            int rem = idx - kk * 340;
            int r = rem / 34, c = rem - r * 34;
            int gy = y0 - 1 + r;
            int gx = x0 - 1 + c;
            float v = 0.f;
            if (gy >= 0 && gy < HH && (unsigned)gx < (unsigned)WW)
                v = in[((size_t)(b*CC + ci0 + kk) * HH + gy) * WW + gx];
            Xs[kk][r][c] = v;
        }
        // ---- load 8-ci weights, duplicated (w,w) for packed math ----
        for (int idx = tid; idx < 8 * 576; idx += 256) {
            int kk  = idx / 576;
            int rem = idx - kk * 576;
            int co = rem / 9, k = rem - co * 9;
            float w = wk[((size_t)co * CC + ci0 + kk) * 9 + k];
            unsigned long long pw; PACKF2(pw, w, w);
            Ws2[kk][k][co] = pw;
        }
        __syncthreads();

        #pragma unroll 1
        for (int kk = 0; kk < 8; kk++) {
            #pragma unroll
            for (int ky = 0; ky < 3; ky++) {
                float xv[10];
                #pragma unroll
                for (int m = 0; m < 10; m++) xv[m] = Xs[kk][row + ky][colg + m];
                unsigned long long xp[9];
                #pragma unroll
                for (int p = 0; p < 9; p++) PACKF2(xp[p], xv[p], xv[p + 1]);
                #pragma unroll
                for (int kx = 0; kx < 3; kx++) {
                    // 8 duplicated weights for this (ci,ky,kx): broadcast LDS.128
                    const ulonglong2* wp =
                        reinterpret_cast<const ulonglong2*>(&Ws2[kk][ky*3 + kx][cog*8]);
                    ulonglong2 w01 = wp[0], w23 = wp[1], w45 = wp[2], w67 = wp[3];
                    unsigned long long wv[8] = { w01.x, w01.y, w23.x, w23.y,
                                                 w45.x, w45.y, w67.x, w67.y };
                    #pragma unroll
                    for (int i = 0; i < 8; i++)
                        #pragma unroll
                        for (int p = 0; p < 4; p++)
                            FFMA2(acc2[i][p], wv[i], xp[2*p + kx]);
                }
            }
        }
        __syncthreads();
    }

    const int y = y0 + row;
    if (y < HP) {
        #pragma unroll
        for (int i = 0; i < 8; i++) {
            int co = cog * 8 + i;
            float o[8];
            #pragma unroll
            for (int p = 0; p < 4; p++) UNPACKF2(o[2*p], o[2*p+1], acc2[i][p]);
            float* op = g_conv + ((size_t)(b*CC + co) * HP + y) * WW + x0 + colg;
            reinterpret_cast<float4*>(op)[0] = make_float4(o[0], o[1], o[2], o[3]);
            reinterpret_cast<float4*>(op)[1] = make_float4(o[4], o[5], o[6], o[7]);
        }
    }
}

// ---------------------------------------------------------------------------
// Top-kernel-row conv T[r] = sum_{ci,kx} W[co,ci,0,kx] * x[ci, r, x+kx-1]
// at the 16 rows in c_R16. grid = (10, 4 row-groups, BB), 256 threads.
// ---------------------------------------------------------------------------
__global__ __launch_bounds__(256)
void trow_kernel(const float* __restrict__ in_ext, const float* __restrict__ wk)
{
    const float* in = in_ext ? in_ext : g_mid;
    __shared__ __align__(16) float Xs4[4][34];
    __shared__ __align__(16) float Ws3[3][64];

    const int x0  = blockIdx.x * 32;
    const int rg  = blockIdx.y;         // 0..3 -> rows c_R16[4*rg .. 4*rg+3]
    const int b   = blockIdx.z;
    const int tid = threadIdx.x;
    const int cog = tid >> 5;           // 0..7
    const int lx  = tid & 31;

    float acc[8][4];
    #pragma unroll
    for (int i = 0; i < 8; i++)
        #pragma unroll
        for (int r = 0; r < 4; r++) acc[i][r] = 0.f;

    for (int ci = 0; ci < CC; ci++) {
        for (int idx = tid; idx < 136; idx += 256) {
            int r = idx / 34, c = idx - r * 34;
            int gy = c_R16[rg*4 + r];           // always in [0,96)
            int gx = x0 - 1 + c;
            float v = 0.f;
            if (gx >= 0 && gx < WW) v = in[((size_t)(b*CC + ci) * HH + gy) * WW + gx];
            Xs4[r][c] = v;
        }
        for (int idx = tid; idx < 192; idx += 256) {
            int co = idx / 3, kx = idx - co * 3;
            Ws3[kx][co] = wk[(co*CC + ci)*9 + kx];   // ky = 0 row
        }
        __syncthreads();

        #pragma unroll
        for (int rr = 0; rr < 4; rr++) {
            float xv[3] = { Xs4[rr][lx], Xs4[rr][lx + 1], Xs4[rr][lx + 2] };
            #pragma unroll
            for (int kx = 0; kx < 3; kx++) {
                const float4* wp = reinterpret_cast<const float4*>(&Ws3[kx][0]) + cog*2;
                float4 wa = wp[0], wb = wp[1];
                float wv[8] = {wa.x, wa.y, wa.z, wa.w, wb.x, wb.y, wb.z, wb.w};
                #pragma unroll
                for (int i = 0; i < 8; i++)
                    acc[i][rr] = fmaf(wv[i], xv[kx], acc[i][rr]);
            }
        }
        __syncthreads();
    }

    #pragma unroll
    for (int i = 0; i < 8; i++) {
        int co = cog*8 + i;
        #pragma unroll
        for (int rr = 0; rr < 4; rr++)
            g_T[((size_t)(b*CC + co) * 16 + rg*4 + rr) * WW + x0 + lx] = acc[i][rr];
    }
}

// ---------------------------------------------------------------------------
// Plane-blend + max + bias + relu.
// out[y] = relu(bias + max_d [(1-w_d)*Cz[y+f_d] + w_d*Cz[y+f_d+1]])  (rows>96 -> 0)
// y==0 subtracts the top-pad correction using g_T.
// grid = (WW/32=10, BB*CC), 256 threads. Shared: full 97-row column strip.
// ---------------------------------------------------------------------------
__global__ __launch_bounds__(256)
void blend_kernel(const float* __restrict__ bias, float* __restrict__ out_ext)
{
    float* out = out_ext ? out_ext : g_mid;
    __shared__ float s[HP][32];

    const int x0  = blockIdx.x * 32;
    const int bc  = blockIdx.y;                 // b*CC + c
    const int tid = threadIdx.x;
    const float* src = g_conv + (size_t)bc * HP * WW + x0;

    for (int idx = tid; idx < HP*32; idx += 256) {
        int r = idx >> 5, c = idx & 31;
        s[r][c] = src[(size_t)r * WW + c];
    }
    __syncthreads();

    const int fi[8]   = {1, 12, 22, 33, 44, 54, 65, 76};
    const float wf[8] = {0.52f, 0.16f, 0.80f, 0.44f, 0.08f, 0.72f, 0.36f, 0.0f};

    const int lx = tid & 31;
    const int ty = tid >> 5;                    // 0..7, each handles 12 rows
    const float bv = bias[bc & (CC - 1)];

    for (int yy = 0; yy < 12; yy++) {
        int y = ty * 12 + yy;
        float m = -3.0e38f;
        #pragma unroll
        for (int d = 0; d < 8; d++) {
            int r0 = y + fi[d];
            float v0 = (r0 <= HH) ? s[r0][lx]     : 0.f;   // row <= 96
            float v1 = (r0 <  HH) ? s[r0 + 1][lx] : 0.f;   // row+1 <= 96
            float v  = (1.f - wf[d]) * v0 + wf[d] * v1;
            m = fmaxf(m, v);
        }
        if (y == 0) {
            // exact top-boundary correction: subtract K_top applied to warpedz[-1]
            m = -3.0e38f;
            #pragma unroll
            for (int d = 0; d < 8; d++) {
                float T0 = g_T[((size_t)bc * 16 + 2*d    ) * WW + x0 + lx];
                float T1 = g_T[((size_t)bc * 16 + 2*d + 1) * WW + x0 + lx];
                float v0 = s[fi[d]][lx]     - T0;
                float v1 = s[fi[d] + 1][lx] - T1;
                float v  = (1.f - wf[d]) * v0 + wf[d] * v1;
                m = fmaxf(m, v);
            }
        }
        out[((size_t)bc * HH + y) * WW + x0 + lx] = fmaxf(m + bv, 0.f);
    }
}

// ---------------------------------------------------------------------------
extern "C" void kernel_launch(void* const* d_in, const int* in_sizes, int n_in,
                              void* d_out, int out_size)
{
    const float* x  = (const float*)d_in[0];
    const float* W1 = (const float*)d_in[1];
    const float* b1 = (const float*)d_in[2];
    const float* W2 = (const float*)d_in[3];
    const float* b2 = (const float*)d_in[4];
    float* out = (float*)d_out;

    dim3 gc(WW/32, (HP + 7) / 8, BB);   // 10 x 13 x 4
    dim3 gt(WW/32, 4, BB);              // 10 x 4  x 4
    dim3 gb(WW/32, BB*CC);              // 10 x 256

    // Layer 1
    conv3_kernel<<<gc, 256>>>(x, W1);
    trow_kernel <<<gt, 256>>>(x, W1);
    blend_kernel<<<gb, 256>>>(b1, nullptr);   // -> g_mid (includes relu)
    // Layer 2
    conv3_kernel<<<gc, 256>>>(nullptr, W2);   // in = g_mid
    trow_kernel <<<gt, 256>>>(nullptr, W2);
    blend_kernel<<<gb, 256>>>(b2, out);
}

// round 8
// speedup vs baseline: 1.2808x; 1.2808x over previous
#include <cuda_runtime.h>
#include <math.h>

#define BB 4
#define CC 64
#define HH 96
#define WW 320
#define HP 97   // conv rows 0..96 (row 96 = top kernel row on x[95])

// Scratch (static device globals: allowed; no runtime allocation)
__device__ float g_conv[BB*CC*HP*WW];   // ~31.8 MB
__device__ float g_mid [BB*CC*HH*WW];   // ~31.5 MB
__device__ float g_T   [BB*CC*16*WW];   // ~5.2 MB  (top-row conv at 16 special rows)

// rows f_d-1, f_d for f = {1,12,22,33,44,54,65,76}
__constant__ int c_R16[16] = {0,1, 11,12, 21,22, 32,33, 43,44, 53,54, 64,65, 75,76};

// ---------------------------------------------------------------------------
// 3x3 SAME conv, zero-extended input, output rows 0..96 into g_conv.
// Block: 64 co x (8 rows x 32 cols) tile, 256 threads, each 8co x 8px.
// ci chunked by 8: ONE load burst + 2 barriers per 8 ci (16 barriers total),
// scalar FFMA inner loop (proven best), 2 blocks/SM for phase overlap.
// grid = (WW/32=10, ceil(HP/8)=13, BB)
// ---------------------------------------------------------------------------
__global__ __launch_bounds__(256, 2)
void conv3_kernel(const float* __restrict__ in_ext, const float* __restrict__ wk)
{
    const float* in = in_ext ? in_ext : g_mid;
    // Xs stride 35: lane addr = (row+ky)*35 + colg + m -> conflict-free per warp.
    __shared__ __align__(16) float Xs[8][10][35];   // 11200 B
    __shared__ __align__(16) float Ws[8][9][64];    // 18432 B   (total 29632 B)

    const int x0  = blockIdx.x * 32;
    const int y0  = blockIdx.y * 8;
    const int b   = blockIdx.z;
    const int tid = threadIdx.x;
    const int cog  = tid >> 5;          // 0..7 : co group (8 co, uniform per warp)
    const int pg   = tid & 31;
    const int row  = pg >> 2;           // 0..7 : tile row
    const int colg = (pg & 3) * 8;      // 0,8,16,24 : col group (8 cols)

    float acc[8][8];
    #pragma unroll
    for (int i = 0; i < 8; i++)
        #pragma unroll
        for (int j = 0; j < 8; j++) acc[i][j] = 0.f;

    #pragma unroll 1
    for (int ci0 = 0; ci0 < CC; ci0 += 8) {
        // ---- X: 8-ci input tile with halo (zero-padded), one burst (MLP~10) ----
        #pragma unroll
        for (int t = 0; t < 11; t++) {
            int idx = t * 256 + tid;                 // 0..2719 (2816 padded, guard)
            if (idx < 8 * 340) {
                int kk  = idx / 340;
                int rem = idx - kk * 340;
                int r = rem / 34, c = rem - r * 34;
                int gy = y0 - 1 + r;
                int gx = x0 - 1 + c;
                float v = 0.f;
                if (gy >= 0 && gy < HH && (unsigned)gx < (unsigned)WW)
                    v = in[((size_t)(b*CC + ci0 + kk) * HH + gy) * WW + gx];
                Xs[kk][r][c] = v;
            }
        }
        // ---- W: 72 contiguous floats per co (8 ci x 9 taps) via LDG.128 ----
        // base float offset = co*576 + ci0*9 (both multiples of 4 -> 16B aligned)
        #pragma unroll
        for (int t = 0; t < 5; t++) {
            int idx = t * 256 + tid;                 // 0..1151 float4s
            if (idx < 64 * 18) {
                int co = idx / 18;
                int j  = idx - co * 18;
                float4 v = reinterpret_cast<const float4*>(
                               wk + (size_t)co * 576 + (size_t)ci0 * 9)[j];
                int f0 = j * 4;
                float vv[4] = {v.x, v.y, v.z, v.w};
                #pragma unroll
                for (int e = 0; e < 4; e++) {
                    int f  = f0 + e;
                    int kk = f / 9;
                    int k  = f - kk * 9;
                    Ws[kk][k][co] = vv[e];
                }
            }
        }
        __syncthreads();

        #pragma unroll 1
        for (int kk = 0; kk < 8; kk++) {
            #pragma unroll
            for (int ky = 0; ky < 3; ky++) {
                float xv[10];
                #pragma unroll
                for (int m = 0; m < 10; m++) xv[m] = Xs[kk][row + ky][colg + m];
                #pragma unroll
                for (int kx = 0; kx < 3; kx++) {
                    const float4* wp =
                        reinterpret_cast<const float4*>(&Ws[kk][ky*3 + kx][0]) + cog*2;
                    float4 wa = wp[0], wb = wp[1];
                    float wv[8] = {wa.x, wa.y, wa.z, wa.w, wb.x, wb.y, wb.z, wb.w};
                    #pragma unroll
                    for (int i = 0; i < 8; i++)
                        #pragma unroll
                        for (int j = 0; j < 8; j++)
                            acc[i][j] = fmaf(wv[i], xv[j + kx], acc[i][j]);
                }
            }
        }
        __syncthreads();
    }

    const int y = y0 + row;
    if (y < HP) {
        #pragma unroll
        for (int i = 0; i < 8; i++) {
            int co = cog * 8 + i;
            float* op = g_conv + ((size_t)(b*CC + co) * HP + y) * WW + x0 + colg;
            reinterpret_cast<float4*>(op)[0] = make_float4(acc[i][0], acc[i][1], acc[i][2], acc[i][3]);
            reinterpret_cast<float4*>(op)[1] = make_float4(acc[i][4], acc[i][5], acc[i][6], acc[i][7]);
        }
    }
}

// ---------------------------------------------------------------------------
// Top-kernel-row conv T[r] = sum_{ci,kx} W[co,ci,0,kx] * x[ci, r, x+kx-1]
// at the 16 rows in c_R16. grid = (10, 4 row-groups, BB), 256 threads.
// ---------------------------------------------------------------------------
__global__ __launch_bounds__(256)
void trow_kernel(const float* __restrict__ in_ext, const float* __restrict__ wk)
{
    const float* in = in_ext ? in_ext : g_mid;
    __shared__ __align__(16) float Xs4[4][34];
    __shared__ __align__(16) float Ws3[3][64];

    const int x0  = blockIdx.x * 32;
    const int rg  = blockIdx.y;         // 0..3 -> rows c_R16[4*rg .. 4*rg+3]
    const int b   = blockIdx.z;
    const int tid = threadIdx.x;
    const int cog = tid >> 5;           // 0..7
    const int lx  = tid & 31;

    float acc[8][4];
    #pragma unroll
    for (int i = 0; i < 8; i++)
        #pragma unroll
        for (int r = 0; r < 4; r++) acc[i][r] = 0.f;

    for (int ci = 0; ci < CC; ci++) {
        for (int idx = tid; idx < 136; idx += 256) {
            int r = idx / 34, c = idx - r * 34;
            int gy = c_R16[rg*4 + r];           // always in [0,96)
            int gx = x0 - 1 + c;
            float v = 0.f;
            if (gx >= 0 && gx < WW) v = in[((size_t)(b*CC + ci) * HH + gy) * WW + gx];
            Xs4[r][c] = v;
        }
        for (int idx = tid; idx < 192; idx += 256) {
            int co = idx / 3, kx = idx - co * 3;
            Ws3[kx][co] = wk[(co*CC + ci)*9 + kx];   // ky = 0 row
        }
        __syncthreads();

        #pragma unroll
        for (int rr = 0; rr < 4; rr++) {
            float xv[3] = { Xs4[rr][lx], Xs4[rr][lx + 1], Xs4[rr][lx + 2] };
            #pragma unroll
            for (int kx = 0; kx < 3; kx++) {
                const float4* wp = reinterpret_cast<const float4*>(&Ws3[kx][0]) + cog*2;
                float4 wa = wp[0], wb = wp[1];
                float wv[8] = {wa.x, wa.y, wa.z, wa.w, wb.x, wb.y, wb.z, wb.w};
                #pragma unroll
                for (int i = 0; i < 8; i++)
                    acc[i][rr] = fmaf(wv[i], xv[kx], acc[i][rr]);
            }
        }
        __syncthreads();
    }

    #pragma unroll
    for (int i = 0; i < 8; i++) {
        int co = cog*8 + i;
        #pragma unroll
        for (int rr = 0; rr < 4; rr++)
            g_T[((size_t)(b*CC + co) * 16 + rg*4 + rr) * WW + x0 + lx] = acc[i][rr];
    }
}

// ---------------------------------------------------------------------------
// Plane-blend + max + bias + relu.
// out[y] = relu(bias + max_d [(1-w_d)*Cz[y+f_d] + w_d*Cz[y+f_d+1]])  (rows>96 -> 0)
// y==0 subtracts the top-pad correction using g_T.
// grid = (WW/32=10, BB*CC), 256 threads. Shared: full 97-row column strip.
// ---------------------------------------------------------------------------
__global__ __launch_bounds__(256)
void blend_kernel(const float* __restrict__ bias, float* __restrict__ out_ext)
{
    float* out = out_ext ? out_ext : g_mid;
    __shared__ float s[HP][32];

    const int x0  = blockIdx.x * 32;
    const int bc  = blockIdx.y;                 // b*CC + c
    const int tid = threadIdx.x;
    const float* src = g_conv + (size_t)bc * HP * WW + x0;

    for (int idx = tid; idx < HP*32; idx += 256) {
        int r = idx >> 5, c = idx & 31;
        s[r][c] = src[(size_t)r * WW + c];
    }
    __syncthreads();

    const int fi[8]   = {1, 12, 22, 33, 44, 54, 65, 76};
    const float wf[8] = {0.52f, 0.16f, 0.80f, 0.44f, 0.08f, 0.72f, 0.36f, 0.0f};

    const int lx = tid & 31;
    const int ty = tid >> 5;                    // 0..7, each handles 12 rows
    const float bv = bias[bc & (CC - 1)];

    for (int yy = 0; yy < 12; yy++) {
        int y = ty * 12 + yy;
        float m = -3.0e38f;
        #pragma unroll
        for (int d = 0; d < 8; d++) {
            int r0 = y + fi[d];
            float v0 = (r0 <= HH) ? s[r0][lx]     : 0.f;   // row <= 96
            float v1 = (r0 <  HH) ? s[r0 + 1][lx] : 0.f;   // row+1 <= 96
            float v  = (1.f - wf[d]) * v0 + wf[d] * v1;
            m = fmaxf(m, v);
        }
        if (y == 0) {
            // exact top-boundary correction: subtract K_top applied to warpedz[-1]
            m = -3.0e38f;
            #pragma unroll
            for (int d = 0; d < 8; d++) {
                float T0 = g_T[((size_t)bc * 16 + 2*d    ) * WW + x0 + lx];
                float T1 = g_T[((size_t)bc * 16 + 2*d + 1) * WW + x0 + lx];
                float v0 = s[fi[d]][lx]     - T0;
                float v1 = s[fi[d] + 1][lx] - T1;
                float v  = (1.f - wf[d]) * v0 + wf[d] * v1;
                m = fmaxf(m, v);
            }
        }
        out[((size_t)bc * HH + y) * WW + x0 + lx] = fmaxf(m + bv, 0.f);
    }
}

// ---------------------------------------------------------------------------
extern "C" void kernel_launch(void* const* d_in, const int* in_sizes, int n_in,
                              void* d_out, int out_size)
{
    const float* x  = (const float*)d_in[0];
    const float* W1 = (const float*)d_in[1];
    const float* b1 = (const float*)d_in[2];
    const float* W2 = (const float*)d_in[3];
    const float* b2 = (const float*)d_in[4];
    float* out = (float*)d_out;

    dim3 gc(WW/32, (HP + 7) / 8, BB);   // 10 x 13 x 4
    dim3 gt(WW/32, 4, BB);              // 10 x 4  x 4
    dim3 gb(WW/32, BB*CC);              // 10 x 256

    // Layer 1
    conv3_kernel<<<gc, 256>>>(x, W1);
    trow_kernel <<<gt, 256>>>(x, W1);
    blend_kernel<<<gb, 256>>>(b1, nullptr);   // -> g_mid (includes relu)
    // Layer 2
    conv3_kernel<<<gc, 256>>>(nullptr, W2);   // in = g_mid
    trow_kernel <<<gt, 256>>>(nullptr, W2);
    blend_kernel<<<gb, 256>>>(b2, out);
}